// round 13
// baseline (speedup 1.0000x reference)
#include <cuda_runtime.h>
#include <cuda_fp16.h>
#include <cstdint>

// Problem constants (fixed by setup_inputs)
#define BB 2
#define LL 4096
#define DD 1024
#define DI 1024
#define NS 16
#define RR 64
#define HH 4096
#define MM (BB*LL)          // 8192 rows
#define PROJC (RR + 2*NS)   // 96
#define SEGS 8
#define SEGL (LL / SEGS)    // 512
#define TB 8

// ---------------- scratch ( __device__ globals, no allocation ) -------------
__device__ __half g_Uh  [(size_t)MM * DD];      // LN(gathered x), fp16
__device__ float  g_XZ  [(size_t)MM * 2 * DI];  // in_proj output (xi | z)
__device__ float  g_XC  [(size_t)MM * DI];      // conv + silu (f32 for scan)
__device__ __half g_XCh [(size_t)MM * DI];      // conv + silu (f16 for GEMM)
__device__ float  g_PROJ[(size_t)MM * PROJC];   // x_proj output (f32 for scan B,C)
__device__ __half g_PROJh[(size_t)MM * PROJC];  // fp16 copy for dt GEMM
__device__ float  g_DT  [(size_t)MM * DI];      // softplus(dt)
__device__ __half g_Yh  [(size_t)MM * DI];      // scan output * silu(z), fp16
__device__ float  g_OUTP[(size_t)MM * DD];      // out_proj output
__device__ float  g_XNEW[(size_t)MM * DD];      // x + scattered mamba out
__device__ __half g_HNh [(size_t)MM * DD];      // LN(xnew), fp16
__device__ __half g_Gh  [(size_t)MM * HH];      // gelu(fc1), fp16
// segmented-scan state
__device__ float g_SegH[(size_t)BB * SEGS * DI * NS];  // partial h per segment
__device__ float g_SegP[(size_t)BB * SEGS * DI * NS];  // prod(dA) per segment
__device__ float g_SegI[(size_t)BB * SEGS * DI * NS];  // h_init per segment
// fp16 weights
__device__ __half g_Wip [(size_t)2 * DI * DD];
__device__ __half g_Wxp [(size_t)PROJC * DI];
__device__ __half g_Wdt [(size_t)DI * RR];
__device__ __half g_Wop [(size_t)DD * DI];
__device__ __half g_Wf1 [(size_t)HH * DD];
__device__ __half g_Wf2 [(size_t)DD * HH];

// ---------------- helpers ---------------------------------------------------
__device__ __forceinline__ float silu_f(float x) { return x / (1.0f + __expf(-x)); }
__device__ __forceinline__ float gelu_tanh_f(float x) {
    float u = 0.7978845608028654f * (x + 0.044715f * x * x * x);
    return 0.5f * x * (1.0f + tanhf(u));
}
__device__ __forceinline__ float softplus_f(float x) {
    return (x > 20.0f) ? x : log1pf(expf(x));
}

// ---------------- f32 -> f16 convert ----------------------------------------
__global__ __launch_bounds__(256) void f2h_kernel(const float* __restrict__ s,
                                                  __half* __restrict__ d, int n)
{
    int i = (blockIdx.x * blockDim.x + threadIdx.x) * 4;
    if (i >= n) return;
    float4 v = *(const float4*)(s + i);
    __half2* dp = (__half2*)(d + i);
    dp[0] = __floats2half2_rn(v.x, v.y);
    dp[1] = __floats2half2_rn(v.z, v.w);
}

// ---------------- LayerNorm (optional gather), fp16 out ---------------------
__global__ __launch_bounds__(256) void ln_kernel(
    const float* __restrict__ X, const int* __restrict__ gather,
    __half* __restrict__ Out)
{
    int row = blockIdx.x;
    int b = row >> 12, t = row & (LL - 1);
    int src = gather ? ((b << 12) + gather[t]) : row;
    const float* xp = X + (size_t)src * DD;
    __half* op = Out + (size_t)row * DD;
    __shared__ float sred[8];
    __shared__ float smv[2];
    int tid = threadIdx.x;

    float v[4];
    float s = 0.f;
#pragma unroll
    for (int i = 0; i < 4; i++) { v[i] = xp[tid + i * 256]; s += v[i]; }
#pragma unroll
    for (int o = 16; o; o >>= 1) s += __shfl_xor_sync(0xffffffffu, s, o);
    if ((tid & 31) == 0) sred[tid >> 5] = s;
    __syncthreads();
    if (tid < 8) {
        s = sred[tid];
#pragma unroll
        for (int o = 4; o; o >>= 1) s += __shfl_xor_sync(0xffu, s, o);
        if (tid == 0) smv[0] = s * (1.0f / DD);
    }
    __syncthreads();
    float mean = smv[0];
    float vs = 0.f;
#pragma unroll
    for (int i = 0; i < 4; i++) { float d = v[i] - mean; vs += d * d; }
#pragma unroll
    for (int o = 16; o; o >>= 1) vs += __shfl_xor_sync(0xffffffffu, vs, o);
    __syncthreads();
    if ((tid & 31) == 0) sred[tid >> 5] = vs;
    __syncthreads();
    if (tid < 8) {
        vs = sred[tid];
#pragma unroll
        for (int o = 4; o; o >>= 1) vs += __shfl_xor_sync(0xffu, vs, o);
        if (tid == 0) smv[1] = rsqrtf(vs * (1.0f / DD) + 1e-6f);
    }
    __syncthreads();
    float inv = smv[1];
#pragma unroll
    for (int i = 0; i < 4; i++) op[tid + i * 256] = __float2half((v[i] - mean) * inv);
}

// ---------------- FP16 tensor-core GEMM (mma.sync) ---------------------------
#define BKH 32
#define ROWH 40   // 32 + 8 pad halfs (80B rows: conflict-free)

__device__ __forceinline__ void mma_f16(float c[4], const uint32_t a[4], const uint32_t b[2]) {
    asm volatile(
        "mma.sync.aligned.m16n8k16.row.col.f32.f16.f16.f32 "
        "{%0,%1,%2,%3}, {%4,%5,%6,%7}, {%8,%9}, {%0,%1,%2,%3};\n"
        : "+f"(c[0]), "+f"(c[1]), "+f"(c[2]), "+f"(c[3])
        : "r"(a[0]), "r"(a[1]), "r"(a[2]), "r"(a[3]), "r"(b[0]), "r"(b[1]));
}
__device__ __forceinline__ void ldsm_x4(uint32_t r[4], const void* p) {
    uint32_t s = (uint32_t)__cvta_generic_to_shared(p);
    asm volatile("ldmatrix.sync.aligned.m8n8.x4.shared.b16 {%0,%1,%2,%3}, [%4];\n"
                 : "=r"(r[0]), "=r"(r[1]), "=r"(r[2]), "=r"(r[3]) : "r"(s));
}
__device__ __forceinline__ void cp16(void* dst, const void* src, bool pred) {
    uint32_t d = (uint32_t)__cvta_generic_to_shared(dst);
    int sz = pred ? 16 : 0;
    asm volatile("cp.async.cg.shared.global [%0], [%1], 16, %2;\n"
                 :: "r"(d), "l"(src), "r"(sz));
}

template <int MODE>
__global__ __launch_bounds__(256, 2) void hgemm(
    const __half* __restrict__ A, int lda,
    const __half* __restrict__ W,
    const float* __restrict__ bias,
    const float* __restrict__ resid,
    float* __restrict__ Cf, __half* __restrict__ Ch,
    int M, int N, int K)
{
    __shared__ __half As[2][128][ROWH];
    __shared__ __half Ws[2][128][ROWH];

    int tid  = threadIdx.x;
    int warp = tid >> 5, lane = tid & 31;
    int g = lane >> 2, t = lane & 3;
    int wm = warp >> 1, wn = warp & 1;     // 4 x 2 warp grid
    int row0 = blockIdx.y * 128;
    int col0 = blockIdx.x * 128;

    int lrow = tid >> 1;
    int lch  = (tid & 1) * 16;
    const __half* Ag = A + (size_t)(row0 + lrow) * lda + lch;
    int wnrow = col0 + lrow;
    bool wok = (wnrow < N);
    const __half* Wg = W + (size_t)(wok ? wnrow : 0) * K + lch;

    int brow_off = ((lane >> 4) << 3) + (lane & 7);   // 0..15
    int bcol_off = ((lane >> 3) & 1) * 8;             // 0 or 8

    float acc[2][8][4];
#pragma unroll
    for (int i = 0; i < 2; i++)
#pragma unroll
        for (int j = 0; j < 8; j++)
#pragma unroll
            for (int q = 0; q < 4; q++) acc[i][j][q] = 0.f;

#define LOADST(k0, b)                                                     \
    {                                                                     \
        cp16(&As[b][lrow][lch + 0], Ag + (k0) + 0, true);                 \
        cp16(&As[b][lrow][lch + 8], Ag + (k0) + 8, true);                 \
        cp16(&Ws[b][lrow][lch + 0], Wg + (k0) + 0, wok);                  \
        cp16(&Ws[b][lrow][lch + 8], Wg + (k0) + 8, wok);                  \
        asm volatile("cp.async.commit_group;\n");                         \
    }

#define COMPUTE(b)                                                        \
    {                                                                     \
        _Pragma("unroll")                                                 \
        for (int ks = 0; ks < BKH; ks += 16) {                            \
            uint32_t af[2][4], bf[8][2];                                  \
            _Pragma("unroll")                                             \
            for (int i = 0; i < 2; i++)                                   \
                ldsm_x4(af[i], &As[b][wm * 32 + i * 16 + (lane & 15)]     \
                                   [ks + (lane >> 4) * 8]);               \
            _Pragma("unroll")                                             \
            for (int p = 0; p < 4; p++) {                                 \
                uint32_t br[4];                                           \
                ldsm_x4(br, &Ws[b][wn * 64 + p * 16 + brow_off]           \
                                  [ks + bcol_off]);                       \
                bf[2 * p + 0][0] = br[0];                                 \
                bf[2 * p + 0][1] = br[1];                                 \
                bf[2 * p + 1][0] = br[2];                                 \
                bf[2 * p + 1][1] = br[3];                                 \
            }                                                             \
            _Pragma("unroll")                                             \
            for (int i = 0; i < 2; i++)                                   \
                _Pragma("unroll")                                         \
                for (int j = 0; j < 8; j++)                               \
                    mma_f16(acc[i][j], af[i], bf[j]);                     \
        }                                                                 \
    }

    LOADST(0, 0);
    int buf = 0;
    for (int k0 = BKH; k0 < K; k0 += BKH) {
        LOADST(k0, buf ^ 1);
        asm volatile("cp.async.wait_group 1;\n");
        __syncthreads();
        COMPUTE(buf);
        __syncthreads();
        buf ^= 1;
    }
    asm volatile("cp.async.wait_group 0;\n");
    __syncthreads();
    COMPUTE(buf);

#pragma unroll
    for (int i = 0; i < 2; i++) {
#pragma unroll
        for (int j = 0; j < 8; j++) {
            int col = col0 + wn * 64 + j * 8 + 2 * t;
            if (col >= N) continue;
            float b0v = 0.f, b1v = 0.f;
            if (MODE == 1 || MODE == 2 || MODE == 3) { b0v = bias[col]; b1v = bias[col + 1]; }
#pragma unroll
            for (int h = 0; h < 2; h++) {
                int row = row0 + wm * 32 + i * 16 + g + h * 8;
                size_t oidx = (size_t)row * N + col;
                float v0 = acc[i][j][2 * h + 0];
                float v1 = acc[i][j][2 * h + 1];
                if (MODE == 1) {
                    v0 = gelu_tanh_f(v0 + b0v); v1 = gelu_tanh_f(v1 + b1v);
                    *(__half2*)(Ch + oidx) = __floats2half2_rn(v0, v1);
                } else if (MODE == 2) {
                    float2 rr = *(const float2*)(resid + oidx);
                    *(float2*)(Cf + oidx) = make_float2(rr.x + v0 + b0v, rr.y + v1 + b1v);
                } else if (MODE == 3) {
                    *(float2*)(Cf + oidx) = make_float2(softplus_f(v0 + b0v),
                                                        softplus_f(v1 + b1v));
                } else if (MODE == 4) {
                    *(float2*)(Cf + oidx) = make_float2(v0, v1);
                    *(__half2*)(Ch + oidx) = __floats2half2_rn(v0, v1);
                } else {
                    *(float2*)(Cf + oidx) = make_float2(v0, v1);
                }
            }
        }
    }
#undef LOADST
#undef COMPUTE
}

// ---------------- depthwise causal conv (D_CONV=4) + silu -------------------
__global__ __launch_bounds__(256) void conv_silu_kernel(
    const float* __restrict__ XZ, const float* __restrict__ conv_w,
    const float* __restrict__ conv_b, float* __restrict__ XC,
    __half* __restrict__ XCh)
{
    size_t idx = (size_t)blockIdx.x * blockDim.x + threadIdx.x;
    if (idx >= (size_t)MM * DI) return;
    int d = (int)(idx & (DI - 1));
    int m = (int)(idx >> 10);
    int t = m & (LL - 1);
    int mb = m - t;
    float acc = conv_b[d];
#pragma unroll
    for (int k = 0; k < 4; k++) {
        int tt = t - 3 + k;
        if (tt >= 0)
            acc = fmaf(conv_w[d * 4 + k], XZ[(size_t)(mb + tt) * (2 * DI) + d], acc);
    }
    float r = silu_f(acc);
    XC[idx] = r;
    XCh[idx] = __float2half(r);
}

// ---------------- segmented selective scan -----------------------------------
// wg -> (b, seg, d):  d = wg & 1023, seg = (wg>>10) & 7, b = wg>>13
// Pass 1: per-segment partial state (h from 0) + prod(dA). No y, no shuffles.
__global__ __launch_bounds__(256) void scan_part1(
    const float* __restrict__ DT, const float* __restrict__ XC,
    const float* __restrict__ PROJ, const float* __restrict__ A_log)
{
    int wg = (blockIdx.x * blockDim.x + threadIdx.x) >> 5;  // 0..16383
    int lane = threadIdx.x & 31;
    int d = wg & (DI - 1);
    int seg = (wg >> 10) & (SEGS - 1);
    int b = wg >> 13;
    bool act = lane < NS;
    float A_n = act ? -expf(A_log[d * NS + lane]) : 0.f;

    size_t rowbase = (size_t)b * LL + (size_t)seg * SEGL;
    const float* dtp = DT + rowbase * DI + d;
    const float* xcp = XC + rowbase * DI + d;
    const float* bcp = PROJ + rowbase * PROJC + RR;

    float cdt[TB], cxc[TB], cbc[TB];
    float ndt[TB] = {0}, nxc[TB] = {0}, nbc[TB] = {0};
#pragma unroll
    for (int i = 0; i < TB; i++) {
        cdt[i] = __ldg(dtp + i * DI);
        cxc[i] = __ldg(xcp + i * DI);
        cbc[i] = __ldg(bcp + i * PROJC + lane);
    }
    float h = 0.f, P = 1.f;
    const int NB = SEGL / TB;
    for (int blk = 0; blk < NB; blk++) {
        if (blk + 1 < NB) {
            const float* dtn = dtp + (blk + 1) * TB * DI;
            const float* xcn = xcp + (blk + 1) * TB * DI;
            const float* bcn = bcp + (blk + 1) * TB * PROJC;
#pragma unroll
            for (int i = 0; i < TB; i++) {
                ndt[i] = __ldg(dtn + i * DI);
                nxc[i] = __ldg(xcn + i * DI);
                nbc[i] = __ldg(bcn + i * PROJC + lane);
            }
        }
#pragma unroll
        for (int i = 0; i < TB; i++) {
            float dt = cdt[i], xc = cxc[i];
            float Bv = act ? cbc[i] : 0.f;
            float dA = __expf(dt * A_n);
            P *= dA;
            h = fmaf(dA, h, dt * xc * Bv);
        }
#pragma unroll
        for (int i = 0; i < TB; i++) { cdt[i] = ndt[i]; cxc[i] = nxc[i]; cbc[i] = nbc[i]; }
    }
    if (act) {
        size_t idx = ((((size_t)b * SEGS + seg) * DI) + d) * NS + lane;
        g_SegH[idx] = h;
        g_SegP[idx] = P;
    }
}

// Pass 2: sequential combine across segments (linearity of the recurrence)
__global__ __launch_bounds__(256) void scan_part2()
{
    int tid = blockIdx.x * blockDim.x + threadIdx.x;   // 0..32767
    int n = tid & (NS - 1);
    int d = (tid >> 4) & (DI - 1);
    int b = tid >> 14;
    float h = 0.f;
#pragma unroll
    for (int s = 0; s < SEGS; s++) {
        size_t idx = ((((size_t)b * SEGS + s) * DI) + d) * NS + n;
        g_SegI[idx] = h;
        h = fmaf(g_SegP[idx], h, g_SegH[idx]);
    }
}

// Pass 3: re-run segment with correct h_init, compute y
__global__ __launch_bounds__(256) void scan_part3(
    const float* __restrict__ DT, const float* __restrict__ XC,
    const float* __restrict__ PROJ, const float* __restrict__ XZ,
    const float* __restrict__ A_log, const float* __restrict__ D_param,
    __half* __restrict__ Y)
{
    int wg = (blockIdx.x * blockDim.x + threadIdx.x) >> 5;  // 0..16383
    int lane = threadIdx.x & 31;
    int d = wg & (DI - 1);
    int seg = (wg >> 10) & (SEGS - 1);
    int b = wg >> 13;
    bool act = lane < NS;
    float A_n = act ? -expf(A_log[d * NS + lane]) : 0.f;
    float Dp = D_param[d];

    size_t rowbase = (size_t)b * LL + (size_t)seg * SEGL;
    const float* dtp = DT + rowbase * DI + d;
    const float* xcp = XC + rowbase * DI + d;
    const float* zp  = XZ + rowbase * (2 * DI) + DI + d;
    const float* bcp = PROJ + rowbase * PROJC + RR;
    __half* yp = Y + rowbase * DI + d;

    float h = 0.f;
    if (act) {
        size_t idx = ((((size_t)b * SEGS + seg) * DI) + d) * NS + lane;
        h = g_SegI[idx];
    }

    float cdt[TB], cxc[TB], czv[TB], cbc[TB];
    float ndt[TB] = {0}, nxc[TB] = {0}, nzv[TB] = {0}, nbc[TB] = {0};
#pragma unroll
    for (int i = 0; i < TB; i++) {
        cdt[i] = __ldg(dtp + i * DI);
        cxc[i] = __ldg(xcp + i * DI);
        czv[i] = __ldg(zp + i * 2 * DI);
        cbc[i] = __ldg(bcp + i * PROJC + lane);
    }
    const int NB = SEGL / TB;
    for (int blk = 0; blk < NB; blk++) {
        if (blk + 1 < NB) {
            const float* dtn = dtp + (blk + 1) * TB * DI;
            const float* xcn = xcp + (blk + 1) * TB * DI;
            const float* zn  = zp  + (blk + 1) * TB * 2 * DI;
            const float* bcn = bcp + (blk + 1) * TB * PROJC;
#pragma unroll
            for (int i = 0; i < TB; i++) {
                ndt[i] = __ldg(dtn + i * DI);
                nxc[i] = __ldg(xcn + i * DI);
                nzv[i] = __ldg(zn + i * 2 * DI);
                nbc[i] = __ldg(bcn + i * PROJC + lane);
            }
        }
        __half* yb = yp + blk * TB * DI;
#pragma unroll
        for (int i = 0; i < TB; i++) {
            float dt = cdt[i], xc = cxc[i], zv = czv[i], bcv = cbc[i];
            float Cv = __shfl_down_sync(0xffffffffu, bcv, 16);
            float Bv = act ? bcv : 0.f;
            Cv = act ? Cv : 0.f;
            float dA = __expf(dt * A_n);
            h = fmaf(dA, h, dt * xc * Bv);
            float part = h * Cv;               // nonzero only in lanes 0-15
#pragma unroll
            for (int o = 8; o; o >>= 1) part += __shfl_xor_sync(0xffffffffu, part, o);
            if (lane == 0) {
                float y = part + Dp * xc;
                yb[i * DI] = __float2half(y * silu_f(zv));
            }
        }
#pragma unroll
        for (int i = 0; i < TB; i++) {
            cdt[i] = ndt[i]; cxc[i] = nxc[i]; czv[i] = nzv[i]; cbc[i] = nbc[i];
        }
    }
}

// ---------------- residual add with gather ----------------------------------
__global__ __launch_bounds__(256) void add_gather_kernel(
    const float* __restrict__ X, const float* __restrict__ OUTP,
    const int* __restrict__ path_rev, float* __restrict__ XNEW)
{
    size_t idx = (size_t)blockIdx.x * blockDim.x + threadIdx.x;
    if (idx >= (size_t)MM * DD) return;
    int d = (int)(idx & (DD - 1));
    int m = (int)(idx >> 10);
    int b = m >> 12, t = m & (LL - 1);
    int src = (b << 12) + path_rev[t];
    XNEW[idx] = X[idx] + OUTP[(size_t)src * DD + d];
}

// ---------------- launch -----------------------------------------------------
extern "C" void kernel_launch(void* const* d_in, const int* in_sizes, int n_in,
                              void* d_out, int out_size)
{
    const float* x          = (const float*)d_in[0];
    const int*   path       = (const int*)  d_in[1];
    const int*   path_rev   = (const int*)  d_in[2];
    const float* in_proj_w  = (const float*)d_in[3];
    const float* conv_w     = (const float*)d_in[4];
    const float* conv_b     = (const float*)d_in[5];
    const float* x_proj_w   = (const float*)d_in[6];
    const float* dt_proj_w  = (const float*)d_in[7];
    const float* dt_proj_b  = (const float*)d_in[8];
    const float* A_log      = (const float*)d_in[9];
    const float* D_param    = (const float*)d_in[10];
    const float* out_proj_w = (const float*)d_in[11];
    const float* fc1_w      = (const float*)d_in[12];
    const float* fc1_b      = (const float*)d_in[13];
    const float* fc2_w      = (const float*)d_in[14];
    const float* fc2_b      = (const float*)d_in[15];
    float* out = (float*)d_out;

    __half *Uh, *XCh, *PROJh, *Yh, *HNh, *Gh;
    __half *Wip, *Wxp, *Wdt, *Wop, *Wf1, *Wf2;
    float *XZ, *XC, *PROJ, *DT, *OUTP, *XNEW;
    cudaGetSymbolAddress((void**)&Uh,    g_Uh);
    cudaGetSymbolAddress((void**)&XZ,    g_XZ);
    cudaGetSymbolAddress((void**)&XC,    g_XC);
    cudaGetSymbolAddress((void**)&XCh,   g_XCh);
    cudaGetSymbolAddress((void**)&PROJ,  g_PROJ);
    cudaGetSymbolAddress((void**)&PROJh, g_PROJh);
    cudaGetSymbolAddress((void**)&DT,    g_DT);
    cudaGetSymbolAddress((void**)&Yh,    g_Yh);
    cudaGetSymbolAddress((void**)&OUTP,  g_OUTP);
    cudaGetSymbolAddress((void**)&XNEW,  g_XNEW);
    cudaGetSymbolAddress((void**)&HNh,   g_HNh);
    cudaGetSymbolAddress((void**)&Gh,    g_Gh);
    cudaGetSymbolAddress((void**)&Wip,   g_Wip);
    cudaGetSymbolAddress((void**)&Wxp,   g_Wxp);
    cudaGetSymbolAddress((void**)&Wdt,   g_Wdt);
    cudaGetSymbolAddress((void**)&Wop,   g_Wop);
    cudaGetSymbolAddress((void**)&Wf1,   g_Wf1);
    cudaGetSymbolAddress((void**)&Wf2,   g_Wf2);

    auto cvt = [&](const float* s, __half* d, int n) {
        f2h_kernel<<<(n / 4 + 255) / 256, 256>>>(s, d, n);
    };

    // 0: f2h Wip
    cvt(in_proj_w,  Wip, 2 * DI * DD);
    // 1: u = LN(x[:, path, :]) -> fp16
    ln_kernel<<<MM, 256>>>(x, path, Uh);
    // 2: f2h Wxp
    cvt(x_proj_w,   Wxp, PROJC * DI);
    // 3: xz = u @ in_proj_w^T   (8192 x 2048, K=1024) -> f32   *** profiled ***
    hgemm<0><<<dim3(2 * DI / 128, MM / 128), 256>>>(
        Uh, DD, Wip, nullptr, nullptr, XZ, nullptr, MM, 2 * DI, DD);
    // 4: conv + silu -> f32 + f16
    conv_silu_kernel<<<(int)(((size_t)MM * DI + 255) / 256), 256>>>(XZ, conv_w, conv_b, XC, XCh);
    // 5: f2h Wdt
    cvt(dt_proj_w,  Wdt, DI * RR);
    // 6: proj = xc @ x_proj_w^T   (8192 x 96, K=1024) -> f32 + f16
    hgemm<4><<<dim3(1, MM / 128), 256>>>(
        XCh, DI, Wxp, nullptr, nullptr, PROJ, PROJh, MM, PROJC, DI);
    // 7: dt = softplus(proj[:, :64] @ dt_proj_w^T + b)   (8192 x 1024, K=64)
    hgemm<3><<<dim3(DI / 128, MM / 128), 256>>>(
        PROJh, PROJC, Wdt, dt_proj_b, nullptr, DT, nullptr, MM, DI, RR);
    // 8-10: segmented selective scan -> Yh
    scan_part1<<<(BB * SEGS * DI * 32) / 256, 256>>>(DT, XC, PROJ, A_log);
    scan_part2<<<(BB * DI * NS) / 256, 256>>>();
    scan_part3<<<(BB * SEGS * DI * 32) / 256, 256>>>(DT, XC, PROJ, XZ, A_log, D_param, Yh);
    // 11: f2h Wop
    cvt(out_proj_w, Wop, DD * DI);
    // 12: OUTP = Y @ out_proj_w^T   (8192 x 1024, K=1024) -> f32
    hgemm<0><<<dim3(DD / 128, MM / 128), 256>>>(
        Yh, DI, Wop, nullptr, nullptr, OUTP, nullptr, MM, DD, DI);
    // 13: xnew = x + OUTP[:, path_rev, :]
    add_gather_kernel<<<(int)(((size_t)MM * DD + 255) / 256), 256>>>(x, OUTP, path_rev, XNEW);
    // 14: hn = LN(xnew) -> fp16
    ln_kernel<<<MM, 256>>>(XNEW, nullptr, HNh);
    // 15: f2h Wf1
    cvt(fc1_w,      Wf1, HH * DD);
    // 16: G = gelu(hn @ fc1_w^T + fc1_b)   (8192 x 4096, K=1024) -> fp16
    hgemm<1><<<dim3(HH / 128, MM / 128), 256>>>(
        HNh, DD, Wf1, fc1_b, nullptr, nullptr, Gh, MM, HH, DD);
    // 17: f2h Wf2
    cvt(fc2_w,      Wf2, DD * HH);
    // 18: out = xnew + G @ fc2_w^T + fc2_b   (8192 x 1024, K=4096)
    hgemm<2><<<dim3(DD / 128, MM / 128), 256>>>(
        Gh, HH, Wf2, fc2_b, XNEW, out, nullptr, MM, DD, HH);
}

// round 14
// speedup vs baseline: 1.7934x; 1.7934x over previous
#include <cuda_runtime.h>
#include <cuda_fp16.h>
#include <cstdint>

// Problem constants (fixed by setup_inputs)
#define BB 2
#define LL 4096
#define DD 1024
#define DI 1024
#define NS 16
#define RR 64
#define HH 4096
#define MM (BB*LL)          // 8192 rows
#define PROJC (RR + 2*NS)   // 96
#define SEGS 16
#define SEGL (LL / SEGS)    // 256
#define TBS 4               // scan prefetch depth (steps)

// ---------------- scratch ( __device__ globals, no allocation ) -------------
__device__ __half g_Uh  [(size_t)MM * DD];
__device__ float  g_XZ  [(size_t)MM * 2 * DI];
__device__ float  g_XC  [(size_t)MM * DI];
__device__ __half g_XCh [(size_t)MM * DI];
__device__ float  g_PROJ[(size_t)MM * PROJC];
__device__ __half g_PROJh[(size_t)MM * PROJC];
__device__ float  g_DT  [(size_t)MM * DI];
__device__ __half g_Yh  [(size_t)MM * DI];
__device__ float  g_OUTP[(size_t)MM * DD];
__device__ float  g_XNEW[(size_t)MM * DD];
__device__ __half g_HNh [(size_t)MM * DD];
__device__ __half g_Gh  [(size_t)MM * HH];
// segmented-scan state: [b][seg][d][n]
__device__ float g_SegH[(size_t)BB * SEGS * DI * NS];
__device__ float g_SegP[(size_t)BB * SEGS * DI * NS];
__device__ float g_SegI[(size_t)BB * SEGS * DI * NS];
// fp16 weights
__device__ __half g_Wip [(size_t)2 * DI * DD];
__device__ __half g_Wxp [(size_t)PROJC * DI];
__device__ __half g_Wdt [(size_t)DI * RR];
__device__ __half g_Wop [(size_t)DD * DI];
__device__ __half g_Wf1 [(size_t)HH * DD];
__device__ __half g_Wf2 [(size_t)DD * HH];

// ---------------- helpers ---------------------------------------------------
__device__ __forceinline__ float silu_f(float x) { return x / (1.0f + __expf(-x)); }
__device__ __forceinline__ float gelu_tanh_f(float x) {
    float u = 0.7978845608028654f * (x + 0.044715f * x * x * x);
    return 0.5f * x * (1.0f + tanhf(u));
}
__device__ __forceinline__ float softplus_f(float x) {
    return (x > 20.0f) ? x : log1pf(expf(x));
}

// ---------------- f32 -> f16 convert ----------------------------------------
__global__ __launch_bounds__(256) void f2h_kernel(const float* __restrict__ s,
                                                  __half* __restrict__ d, int n)
{
    int i = (blockIdx.x * blockDim.x + threadIdx.x) * 4;
    if (i >= n) return;
    float4 v = *(const float4*)(s + i);
    __half2* dp = (__half2*)(d + i);
    dp[0] = __floats2half2_rn(v.x, v.y);
    dp[1] = __floats2half2_rn(v.z, v.w);
}

// ---------------- LayerNorm (optional gather), fp16 out ---------------------
__global__ __launch_bounds__(256) void ln_kernel(
    const float* __restrict__ X, const int* __restrict__ gather,
    __half* __restrict__ Out)
{
    int row = blockIdx.x;
    int b = row >> 12, t = row & (LL - 1);
    int src = gather ? ((b << 12) + gather[t]) : row;
    const float* xp = X + (size_t)src * DD;
    __half* op = Out + (size_t)row * DD;
    __shared__ float sred[8];
    __shared__ float smv[2];
    int tid = threadIdx.x;

    float v[4];
    float s = 0.f;
#pragma unroll
    for (int i = 0; i < 4; i++) { v[i] = xp[tid + i * 256]; s += v[i]; }
#pragma unroll
    for (int o = 16; o; o >>= 1) s += __shfl_xor_sync(0xffffffffu, s, o);
    if ((tid & 31) == 0) sred[tid >> 5] = s;
    __syncthreads();
    if (tid < 8) {
        s = sred[tid];
#pragma unroll
        for (int o = 4; o; o >>= 1) s += __shfl_xor_sync(0xffu, s, o);
        if (tid == 0) smv[0] = s * (1.0f / DD);
    }
    __syncthreads();
    float mean = smv[0];
    float vs = 0.f;
#pragma unroll
    for (int i = 0; i < 4; i++) { float d = v[i] - mean; vs += d * d; }
#pragma unroll
    for (int o = 16; o; o >>= 1) vs += __shfl_xor_sync(0xffffffffu, vs, o);
    __syncthreads();
    if ((tid & 31) == 0) sred[tid >> 5] = vs;
    __syncthreads();
    if (tid < 8) {
        vs = sred[tid];
#pragma unroll
        for (int o = 4; o; o >>= 1) vs += __shfl_xor_sync(0xffu, vs, o);
        if (tid == 0) smv[1] = rsqrtf(vs * (1.0f / DD) + 1e-6f);
    }
    __syncthreads();
    float inv = smv[1];
#pragma unroll
    for (int i = 0; i < 4; i++) op[tid + i * 256] = __float2half((v[i] - mean) * inv);
}

// ---------------- FP16 tensor-core GEMM (mma.sync) ---------------------------
#define BKH 32
#define ROWH 40   // 32 + 8 pad halfs (80B rows: conflict-free)

__device__ __forceinline__ void mma_f16(float c[4], const uint32_t a[4], const uint32_t b[2]) {
    asm volatile(
        "mma.sync.aligned.m16n8k16.row.col.f32.f16.f16.f32 "
        "{%0,%1,%2,%3}, {%4,%5,%6,%7}, {%8,%9}, {%0,%1,%2,%3};\n"
        : "+f"(c[0]), "+f"(c[1]), "+f"(c[2]), "+f"(c[3])
        : "r"(a[0]), "r"(a[1]), "r"(a[2]), "r"(a[3]), "r"(b[0]), "r"(b[1]));
}
__device__ __forceinline__ void ldsm_x4(uint32_t r[4], const void* p) {
    uint32_t s = (uint32_t)__cvta_generic_to_shared(p);
    asm volatile("ldmatrix.sync.aligned.m8n8.x4.shared.b16 {%0,%1,%2,%3}, [%4];\n"
                 : "=r"(r[0]), "=r"(r[1]), "=r"(r[2]), "=r"(r[3]) : "r"(s));
}
__device__ __forceinline__ void cp16(void* dst, const void* src, bool pred) {
    uint32_t d = (uint32_t)__cvta_generic_to_shared(dst);
    int sz = pred ? 16 : 0;
    asm volatile("cp.async.cg.shared.global [%0], [%1], 16, %2;\n"
                 :: "r"(d), "l"(src), "r"(sz));
}

template <int MODE>
__global__ __launch_bounds__(256, 2) void hgemm(
    const __half* __restrict__ A, int lda,
    const __half* __restrict__ W,
    const float* __restrict__ bias,
    const float* __restrict__ resid,
    float* __restrict__ Cf, __half* __restrict__ Ch,
    int M, int N, int K)
{
    __shared__ __half As[2][128][ROWH];
    __shared__ __half Ws[2][128][ROWH];

    int tid  = threadIdx.x;
    int warp = tid >> 5, lane = tid & 31;
    int g = lane >> 2, t = lane & 3;
    int wm = warp >> 1, wn = warp & 1;
    int row0 = blockIdx.y * 128;
    int col0 = blockIdx.x * 128;

    int lrow = tid >> 1;
    int lch  = (tid & 1) * 16;
    const __half* Ag = A + (size_t)(row0 + lrow) * lda + lch;
    int wnrow = col0 + lrow;
    bool wok = (wnrow < N);
    const __half* Wg = W + (size_t)(wok ? wnrow : 0) * K + lch;

    int brow_off = ((lane >> 4) << 3) + (lane & 7);
    int bcol_off = ((lane >> 3) & 1) * 8;

    float acc[2][8][4];
#pragma unroll
    for (int i = 0; i < 2; i++)
#pragma unroll
        for (int j = 0; j < 8; j++)
#pragma unroll
            for (int q = 0; q < 4; q++) acc[i][j][q] = 0.f;

#define LOADST(k0, b)                                                     \
    {                                                                     \
        cp16(&As[b][lrow][lch + 0], Ag + (k0) + 0, true);                 \
        cp16(&As[b][lrow][lch + 8], Ag + (k0) + 8, true);                 \
        cp16(&Ws[b][lrow][lch + 0], Wg + (k0) + 0, wok);                  \
        cp16(&Ws[b][lrow][lch + 8], Wg + (k0) + 8, wok);                  \
        asm volatile("cp.async.commit_group;\n");                         \
    }

#define COMPUTE(b)                                                        \
    {                                                                     \
        _Pragma("unroll")                                                 \
        for (int ks = 0; ks < BKH; ks += 16) {                            \
            uint32_t af[2][4], bf[8][2];                                  \
            _Pragma("unroll")                                             \
            for (int i = 0; i < 2; i++)                                   \
                ldsm_x4(af[i], &As[b][wm * 32 + i * 16 + (lane & 15)]     \
                                   [ks + (lane >> 4) * 8]);               \
            _Pragma("unroll")                                             \
            for (int p = 0; p < 4; p++) {                                 \
                uint32_t br[4];                                           \
                ldsm_x4(br, &Ws[b][wn * 64 + p * 16 + brow_off]           \
                                  [ks + bcol_off]);                       \
                bf[2 * p + 0][0] = br[0];                                 \
                bf[2 * p + 0][1] = br[1];                                 \
                bf[2 * p + 1][0] = br[2];                                 \
                bf[2 * p + 1][1] = br[3];                                 \
            }                                                             \
            _Pragma("unroll")                                             \
            for (int i = 0; i < 2; i++)                                   \
                _Pragma("unroll")                                         \
                for (int j = 0; j < 8; j++)                               \
                    mma_f16(acc[i][j], af[i], bf[j]);                     \
        }                                                                 \
    }

    LOADST(0, 0);
    int buf = 0;
    for (int k0 = BKH; k0 < K; k0 += BKH) {
        LOADST(k0, buf ^ 1);
        asm volatile("cp.async.wait_group 1;\n");
        __syncthreads();
        COMPUTE(buf);
        __syncthreads();
        buf ^= 1;
    }
    asm volatile("cp.async.wait_group 0;\n");
    __syncthreads();
    COMPUTE(buf);

#pragma unroll
    for (int i = 0; i < 2; i++) {
#pragma unroll
        for (int j = 0; j < 8; j++) {
            int col = col0 + wn * 64 + j * 8 + 2 * t;
            if (col >= N) continue;
            float b0v = 0.f, b1v = 0.f;
            if (MODE == 1 || MODE == 2 || MODE == 3) { b0v = bias[col]; b1v = bias[col + 1]; }
#pragma unroll
            for (int h = 0; h < 2; h++) {
                int row = row0 + wm * 32 + i * 16 + g + h * 8;
                size_t oidx = (size_t)row * N + col;
                float v0 = acc[i][j][2 * h + 0];
                float v1 = acc[i][j][2 * h + 1];
                if (MODE == 1) {
                    v0 = gelu_tanh_f(v0 + b0v); v1 = gelu_tanh_f(v1 + b1v);
                    *(__half2*)(Ch + oidx) = __floats2half2_rn(v0, v1);
                } else if (MODE == 2) {
                    float2 rr = *(const float2*)(resid + oidx);
                    *(float2*)(Cf + oidx) = make_float2(rr.x + v0 + b0v, rr.y + v1 + b1v);
                } else if (MODE == 3) {
                    *(float2*)(Cf + oidx) = make_float2(softplus_f(v0 + b0v),
                                                        softplus_f(v1 + b1v));
                } else if (MODE == 4) {
                    *(float2*)(Cf + oidx) = make_float2(v0, v1);
                    *(__half2*)(Ch + oidx) = __floats2half2_rn(v0, v1);
                } else {
                    *(float2*)(Cf + oidx) = make_float2(v0, v1);
                }
            }
        }
    }
#undef LOADST
#undef COMPUTE
}

// ---------------- depthwise causal conv (D_CONV=4) + silu -------------------
__global__ __launch_bounds__(256) void conv_silu_kernel(
    const float* __restrict__ XZ, const float* __restrict__ conv_w,
    const float* __restrict__ conv_b, float* __restrict__ XC,
    __half* __restrict__ XCh)
{
    size_t idx = (size_t)blockIdx.x * blockDim.x + threadIdx.x;
    if (idx >= (size_t)MM * DI) return;
    int d = (int)(idx & (DI - 1));
    int m = (int)(idx >> 10);
    int t = m & (LL - 1);
    int mb = m - t;
    float acc = conv_b[d];
#pragma unroll
    for (int k = 0; k < 4; k++) {
        int tt = t - 3 + k;
        if (tt >= 0)
            acc = fmaf(conv_w[d * 4 + k], XZ[(size_t)(mb + tt) * (2 * DI) + d], acc);
    }
    float r = silu_f(acc);
    XC[idx] = r;
    XCh[idx] = __float2half(r);
}

// ---------------- segmented selective scan: THREAD-PER-CHANNEL ---------------
// warp wg -> (b, grp, seg): seg = wg & 15, grp = (wg>>4) & 31, b = wg >> 9
// lane owns channel d = grp*32 + lane; 16 states in registers.
// B/C at step t: coalesced 128B load of PROJ[.., RR..RR+32), distributed via shfl.

// Pass 1: from h=0 over segment -> SegH (partial state), SegP (prod dA)
__global__ __launch_bounds__(256) void scan_part1(
    const float* __restrict__ DT, const float* __restrict__ XC,
    const float* __restrict__ PROJ, const float* __restrict__ A_log)
{
    int wg = (blockIdx.x * blockDim.x + threadIdx.x) >> 5;  // 0..1023
    int lane = threadIdx.x & 31;
    int seg = wg & (SEGS - 1);
    int grp = (wg >> 4) & 31;
    int b = wg >> 9;
    int d = grp * 32 + lane;

    float An[NS];
#pragma unroll
    for (int n = 0; n < NS; n++) An[n] = -expf(A_log[d * NS + n]);

    size_t rowbase = (size_t)b * LL + (size_t)seg * SEGL;
    const float* dtp = DT + rowbase * DI + d;
    const float* xcp = XC + rowbase * DI + d;
    const float* bcp = PROJ + rowbase * PROJC + RR + lane;

    float h[NS], P[NS];
#pragma unroll
    for (int n = 0; n < NS; n++) { h[n] = 0.f; P[n] = 1.f; }

    float cdt[TBS], cxc[TBS], cbc[TBS];
    float ndt[TBS] = {0}, nxc[TBS] = {0}, nbc[TBS] = {0};
#pragma unroll
    for (int i = 0; i < TBS; i++) {
        cdt[i] = __ldg(dtp + i * DI);
        cxc[i] = __ldg(xcp + i * DI);
        cbc[i] = __ldg(bcp + i * PROJC);
    }
    const int NB = SEGL / TBS;
    for (int blk = 0; blk < NB; blk++) {
        if (blk + 1 < NB) {
            const float* dtn = dtp + (blk + 1) * TBS * DI;
            const float* xcn = xcp + (blk + 1) * TBS * DI;
            const float* bcn = bcp + (blk + 1) * TBS * PROJC;
#pragma unroll
            for (int i = 0; i < TBS; i++) {
                ndt[i] = __ldg(dtn + i * DI);
                nxc[i] = __ldg(xcn + i * DI);
                nbc[i] = __ldg(bcn + i * PROJC);
            }
        }
#pragma unroll
        for (int i = 0; i < TBS; i++) {
            float dt = cdt[i];
            float u = dt * cxc[i];
            float bcv = cbc[i];
#pragma unroll
            for (int n = 0; n < NS; n++) {
                float Bn = __shfl_sync(0xffffffffu, bcv, n);
                float dA = __expf(dt * An[n]);
                P[n] *= dA;
                h[n] = fmaf(dA, h[n], u * Bn);
            }
        }
#pragma unroll
        for (int i = 0; i < TBS; i++) { cdt[i] = ndt[i]; cxc[i] = nxc[i]; cbc[i] = nbc[i]; }
    }
    size_t idx = ((((size_t)b * SEGS + seg) * DI) + d) * NS;
#pragma unroll
    for (int n = 0; n < NS; n += 4) {
        *(float4*)(g_SegH + idx + n) = make_float4(h[n], h[n+1], h[n+2], h[n+3]);
        *(float4*)(g_SegP + idx + n) = make_float4(P[n], P[n+1], P[n+2], P[n+3]);
    }
}

// Pass 2: sequential combine across segments
__global__ __launch_bounds__(256) void scan_part2()
{
    int tid = blockIdx.x * blockDim.x + threadIdx.x;   // 0..32767
    int n = tid & (NS - 1);
    int d = (tid >> 4) & (DI - 1);
    int b = tid >> 14;
    float h = 0.f;
#pragma unroll
    for (int s = 0; s < SEGS; s++) {
        size_t idx = ((((size_t)b * SEGS + s) * DI) + d) * NS + n;
        g_SegI[idx] = h;
        h = fmaf(g_SegP[idx], h, g_SegH[idx]);
    }
}

// Pass 3: re-run segment with h_init, produce y
__global__ __launch_bounds__(256) void scan_part3(
    const float* __restrict__ DT, const float* __restrict__ XC,
    const float* __restrict__ PROJ, const float* __restrict__ XZ,
    const float* __restrict__ A_log, const float* __restrict__ D_param,
    __half* __restrict__ Y)
{
    int wg = (blockIdx.x * blockDim.x + threadIdx.x) >> 5;  // 0..1023
    int lane = threadIdx.x & 31;
    int seg = wg & (SEGS - 1);
    int grp = (wg >> 4) & 31;
    int b = wg >> 9;
    int d = grp * 32 + lane;

    float An[NS];
#pragma unroll
    for (int n = 0; n < NS; n++) An[n] = -expf(A_log[d * NS + n]);
    float Dp = D_param[d];

    size_t rowbase = (size_t)b * LL + (size_t)seg * SEGL;
    const float* dtp = DT + rowbase * DI + d;
    const float* xcp = XC + rowbase * DI + d;
    const float* zp  = XZ + rowbase * (2 * DI) + DI + d;
    const float* bcp = PROJ + rowbase * PROJC + RR + lane;
    __half* yp = Y + rowbase * DI + d;

    float h[NS];
    {
        size_t idx = ((((size_t)b * SEGS + seg) * DI) + d) * NS;
#pragma unroll
        for (int n = 0; n < NS; n += 4) {
            float4 v = *(const float4*)(g_SegI + idx + n);
            h[n] = v.x; h[n+1] = v.y; h[n+2] = v.z; h[n+3] = v.w;
        }
    }

    float cdt[TBS], cxc[TBS], czv[TBS], cbc[TBS];
    float ndt[TBS] = {0}, nxc[TBS] = {0}, nzv[TBS] = {0}, nbc[TBS] = {0};
#pragma unroll
    for (int i = 0; i < TBS; i++) {
        cdt[i] = __ldg(dtp + i * DI);
        cxc[i] = __ldg(xcp + i * DI);
        czv[i] = __ldg(zp + i * 2 * DI);
        cbc[i] = __ldg(bcp + i * PROJC);
    }
    const int NB = SEGL / TBS;
    for (int blk = 0; blk < NB; blk++) {
        if (blk + 1 < NB) {
            const float* dtn = dtp + (blk + 1) * TBS * DI;
            const float* xcn = xcp + (blk + 1) * TBS * DI;
            const float* zn  = zp  + (blk + 1) * TBS * 2 * DI;
            const float* bcn = bcp + (blk + 1) * TBS * PROJC;
#pragma unroll
            for (int i = 0; i < TBS; i++) {
                ndt[i] = __ldg(dtn + i * DI);
                nxc[i] = __ldg(xcn + i * DI);
                nzv[i] = __ldg(zn + i * 2 * DI);
                nbc[i] = __ldg(bcn + i * PROJC);
            }
        }
        __half* yb = yp + blk * TBS * DI;
#pragma unroll
        for (int i = 0; i < TBS; i++) {
            float dt = cdt[i], xc = cxc[i];
            float u = dt * xc;
            float bcv = cbc[i];
            float y = 0.f;
#pragma unroll
            for (int n = 0; n < NS; n++) {
                float Bn = __shfl_sync(0xffffffffu, bcv, n);
                float Cn = __shfl_sync(0xffffffffu, bcv, NS + n);
                float dA = __expf(dt * An[n]);
                h[n] = fmaf(dA, h[n], u * Bn);
                y = fmaf(h[n], Cn, y);
            }
            y = fmaf(Dp, xc, y);
            yb[i * DI] = __float2half(y * silu_f(czv[i]));
        }
#pragma unroll
        for (int i = 0; i < TBS; i++) {
            cdt[i] = ndt[i]; cxc[i] = nxc[i]; czv[i] = nzv[i]; cbc[i] = nbc[i];
        }
    }
}

// ---------------- residual add with gather ----------------------------------
__global__ __launch_bounds__(256) void add_gather_kernel(
    const float* __restrict__ X, const float* __restrict__ OUTP,
    const int* __restrict__ path_rev, float* __restrict__ XNEW)
{
    size_t idx = (size_t)blockIdx.x * blockDim.x + threadIdx.x;
    if (idx >= (size_t)MM * DD) return;
    int d = (int)(idx & (DD - 1));
    int m = (int)(idx >> 10);
    int b = m >> 12, t = m & (LL - 1);
    int src = (b << 12) + path_rev[t];
    XNEW[idx] = X[idx] + OUTP[(size_t)src * DD + d];
}

// ---------------- launch -----------------------------------------------------
extern "C" void kernel_launch(void* const* d_in, const int* in_sizes, int n_in,
                              void* d_out, int out_size)
{
    const float* x          = (const float*)d_in[0];
    const int*   path       = (const int*)  d_in[1];
    const int*   path_rev   = (const int*)  d_in[2];
    const float* in_proj_w  = (const float*)d_in[3];
    const float* conv_w     = (const float*)d_in[4];
    const float* conv_b     = (const float*)d_in[5];
    const float* x_proj_w   = (const float*)d_in[6];
    const float* dt_proj_w  = (const float*)d_in[7];
    const float* dt_proj_b  = (const float*)d_in[8];
    const float* A_log      = (const float*)d_in[9];
    const float* D_param    = (const float*)d_in[10];
    const float* out_proj_w = (const float*)d_in[11];
    const float* fc1_w      = (const float*)d_in[12];
    const float* fc1_b      = (const float*)d_in[13];
    const float* fc2_w      = (const float*)d_in[14];
    const float* fc2_b      = (const float*)d_in[15];
    float* out = (float*)d_out;

    __half *Uh, *XCh, *PROJh, *Yh, *HNh, *Gh;
    __half *Wip, *Wxp, *Wdt, *Wop, *Wf1, *Wf2;
    float *XZ, *XC, *PROJ, *DT, *OUTP, *XNEW;
    cudaGetSymbolAddress((void**)&Uh,    g_Uh);
    cudaGetSymbolAddress((void**)&XZ,    g_XZ);
    cudaGetSymbolAddress((void**)&XC,    g_XC);
    cudaGetSymbolAddress((void**)&XCh,   g_XCh);
    cudaGetSymbolAddress((void**)&PROJ,  g_PROJ);
    cudaGetSymbolAddress((void**)&PROJh, g_PROJh);
    cudaGetSymbolAddress((void**)&DT,    g_DT);
    cudaGetSymbolAddress((void**)&Yh,    g_Yh);
    cudaGetSymbolAddress((void**)&OUTP,  g_OUTP);
    cudaGetSymbolAddress((void**)&XNEW,  g_XNEW);
    cudaGetSymbolAddress((void**)&HNh,   g_HNh);
    cudaGetSymbolAddress((void**)&Gh,    g_Gh);
    cudaGetSymbolAddress((void**)&Wip,   g_Wip);
    cudaGetSymbolAddress((void**)&Wxp,   g_Wxp);
    cudaGetSymbolAddress((void**)&Wdt,   g_Wdt);
    cudaGetSymbolAddress((void**)&Wop,   g_Wop);
    cudaGetSymbolAddress((void**)&Wf1,   g_Wf1);
    cudaGetSymbolAddress((void**)&Wf2,   g_Wf2);

    auto cvt = [&](const float* s, __half* d, int n) {
        f2h_kernel<<<(n / 4 + 255) / 256, 256>>>(s, d, n);
    };

    // 0: f2h Wip
    cvt(in_proj_w,  Wip, 2 * DI * DD);
    // 1: u = LN(x[:, path, :]) -> fp16
    ln_kernel<<<MM, 256>>>(x, path, Uh);
    // 2: f2h Wxp
    cvt(x_proj_w,   Wxp, PROJC * DI);
    // 3: xz = u @ in_proj_w^T   (8192 x 2048, K=1024) -> f32   *** profiled ***
    hgemm<0><<<dim3(2 * DI / 128, MM / 128), 256>>>(
        Uh, DD, Wip, nullptr, nullptr, XZ, nullptr, MM, 2 * DI, DD);
    // 4: conv + silu -> f32 + f16
    conv_silu_kernel<<<(int)(((size_t)MM * DI + 255) / 256), 256>>>(XZ, conv_w, conv_b, XC, XCh);
    // 5: f2h Wdt
    cvt(dt_proj_w,  Wdt, DI * RR);
    // 6: proj = xc @ x_proj_w^T   (8192 x 96, K=1024) -> f32 + f16
    hgemm<4><<<dim3(1, MM / 128), 256>>>(
        XCh, DI, Wxp, nullptr, nullptr, PROJ, PROJh, MM, PROJC, DI);
    // 7: dt = softplus(proj[:, :64] @ dt_proj_w^T + b)   (8192 x 1024, K=64)
    hgemm<3><<<dim3(DI / 128, MM / 128), 256>>>(
        PROJh, PROJC, Wdt, dt_proj_b, nullptr, DT, nullptr, MM, DI, RR);
    // 8-10: segmented thread-per-channel scan -> Yh
    scan_part1<<<(BB * SEGS * 32 * 32) / 256, 256>>>(DT, XC, PROJ, A_log);
    scan_part2<<<(BB * DI * NS) / 256, 256>>>();
    scan_part3<<<(BB * SEGS * 32 * 32) / 256, 256>>>(DT, XC, PROJ, XZ, A_log, D_param, Yh);
    // 11: f2h Wop
    cvt(out_proj_w, Wop, DD * DI);
    // 12: OUTP = Y @ out_proj_w^T   (8192 x 1024, K=1024) -> f32
    hgemm<0><<<dim3(DD / 128, MM / 128), 256>>>(
        Yh, DI, Wop, nullptr, nullptr, OUTP, nullptr, MM, DD, DI);
    // 13: xnew = x + OUTP[:, path_rev, :]
    add_gather_kernel<<<(int)(((size_t)MM * DD + 255) / 256), 256>>>(x, OUTP, path_rev, XNEW);
    // 14: hn = LN(xnew) -> fp16
    ln_kernel<<<MM, 256>>>(XNEW, nullptr, HNh);
    // 15: f2h Wf1
    cvt(fc1_w,      Wf1, HH * DD);
    // 16: G = gelu(hn @ fc1_w^T + fc1_b)   (8192 x 4096, K=1024) -> fp16
    hgemm<1><<<dim3(HH / 128, MM / 128), 256>>>(
        HNh, DD, Wf1, fc1_b, nullptr, nullptr, Gh, MM, HH, DD);
    // 17: f2h Wf2
    cvt(fc2_w,      Wf2, DD * HH);
    // 18: out = xnew + G @ fc2_w^T + fc2_b   (8192 x 1024, K=4096)
    hgemm<2><<<dim3(DD / 128, MM / 128), 256>>>(
        Gh, HH, Wf2, fc2_b, XNEW, out, nullptr, MM, DD, HH);
}

// round 15
// speedup vs baseline: 1.8078x; 1.0081x over previous
#include <cuda_runtime.h>
#include <cuda_fp16.h>
#include <cstdint>

// Problem constants (fixed by setup_inputs)
#define BB 2
#define LL 4096
#define DD 1024
#define DI 1024
#define NS 16
#define RR 64
#define HH 4096
#define MM (BB*LL)          // 8192 rows
#define PROJC (RR + 2*NS)   // 96
#define SEGS 32
#define SEGL (LL / SEGS)    // 128
#define TBS 8               // scan prefetch depth (steps)

// ---------------- scratch ( __device__ globals, no allocation ) -------------
__device__ __half g_Uh  [(size_t)MM * DD];
__device__ float  g_XZ  [(size_t)MM * 2 * DI];
__device__ float  g_XC  [(size_t)MM * DI];
__device__ __half g_XCh [(size_t)MM * DI];
__device__ float  g_PROJ[(size_t)MM * PROJC];
__device__ __half g_PROJh[(size_t)MM * PROJC];
__device__ float  g_DT  [(size_t)MM * DI];
__device__ __half g_Yh  [(size_t)MM * DI];
__device__ float  g_OUTP[(size_t)MM * DD];
__device__ float  g_XNEW[(size_t)MM * DD];
__device__ __half g_HNh [(size_t)MM * DD];
__device__ __half g_Gh  [(size_t)MM * HH];
// segmented-scan state: [b][seg][d][n]
__device__ float g_SegH[(size_t)BB * SEGS * DI * NS];
__device__ float g_SegP[(size_t)BB * SEGS * DI * NS];
__device__ float g_SegI[(size_t)BB * SEGS * DI * NS];
// fp16 weights
__device__ __half g_Wip [(size_t)2 * DI * DD];
__device__ __half g_Wxp [(size_t)PROJC * DI];
__device__ __half g_Wdt [(size_t)DI * RR];
__device__ __half g_Wop [(size_t)DD * DI];
__device__ __half g_Wf1 [(size_t)HH * DD];
__device__ __half g_Wf2 [(size_t)DD * HH];

// ---------------- helpers ---------------------------------------------------
__device__ __forceinline__ float silu_f(float x) { return x / (1.0f + __expf(-x)); }
__device__ __forceinline__ float gelu_tanh_f(float x) {
    float u = 0.7978845608028654f * (x + 0.044715f * x * x * x);
    return 0.5f * x * (1.0f + tanhf(u));
}
__device__ __forceinline__ float softplus_f(float x) {
    return (x > 20.0f) ? x : log1pf(expf(x));
}

// ---------------- f32 -> f16 convert ----------------------------------------
__global__ __launch_bounds__(256) void f2h_kernel(const float* __restrict__ s,
                                                  __half* __restrict__ d, int n)
{
    int i = (blockIdx.x * blockDim.x + threadIdx.x) * 4;
    if (i >= n) return;
    float4 v = *(const float4*)(s + i);
    __half2* dp = (__half2*)(d + i);
    dp[0] = __floats2half2_rn(v.x, v.y);
    dp[1] = __floats2half2_rn(v.z, v.w);
}

// ---------------- LayerNorm (optional gather), fp16 out ---------------------
__global__ __launch_bounds__(256) void ln_kernel(
    const float* __restrict__ X, const int* __restrict__ gather,
    __half* __restrict__ Out)
{
    int row = blockIdx.x;
    int b = row >> 12, t = row & (LL - 1);
    int src = gather ? ((b << 12) + gather[t]) : row;
    const float* xp = X + (size_t)src * DD;
    __half* op = Out + (size_t)row * DD;
    __shared__ float sred[8];
    __shared__ float smv[2];
    int tid = threadIdx.x;

    float v[4];
    float s = 0.f;
#pragma unroll
    for (int i = 0; i < 4; i++) { v[i] = xp[tid + i * 256]; s += v[i]; }
#pragma unroll
    for (int o = 16; o; o >>= 1) s += __shfl_xor_sync(0xffffffffu, s, o);
    if ((tid & 31) == 0) sred[tid >> 5] = s;
    __syncthreads();
    if (tid < 8) {
        s = sred[tid];
#pragma unroll
        for (int o = 4; o; o >>= 1) s += __shfl_xor_sync(0xffu, s, o);
        if (tid == 0) smv[0] = s * (1.0f / DD);
    }
    __syncthreads();
    float mean = smv[0];
    float vs = 0.f;
#pragma unroll
    for (int i = 0; i < 4; i++) { float d = v[i] - mean; vs += d * d; }
#pragma unroll
    for (int o = 16; o; o >>= 1) vs += __shfl_xor_sync(0xffffffffu, vs, o);
    __syncthreads();
    if ((tid & 31) == 0) sred[tid >> 5] = vs;
    __syncthreads();
    if (tid < 8) {
        vs = sred[tid];
#pragma unroll
        for (int o = 4; o; o >>= 1) vs += __shfl_xor_sync(0xffu, vs, o);
        if (tid == 0) smv[1] = rsqrtf(vs * (1.0f / DD) + 1e-6f);
    }
    __syncthreads();
    float inv = smv[1];
#pragma unroll
    for (int i = 0; i < 4; i++) op[tid + i * 256] = __float2half((v[i] - mean) * inv);
}

// ---------------- FP16 tensor-core GEMM (mma.sync) ---------------------------
#define BKH 32
#define ROWH 40   // 32 + 8 pad halfs (80B rows: conflict-free)

__device__ __forceinline__ void mma_f16(float c[4], const uint32_t a[4], const uint32_t b[2]) {
    asm volatile(
        "mma.sync.aligned.m16n8k16.row.col.f32.f16.f16.f32 "
        "{%0,%1,%2,%3}, {%4,%5,%6,%7}, {%8,%9}, {%0,%1,%2,%3};\n"
        : "+f"(c[0]), "+f"(c[1]), "+f"(c[2]), "+f"(c[3])
        : "r"(a[0]), "r"(a[1]), "r"(a[2]), "r"(a[3]), "r"(b[0]), "r"(b[1]));
}
__device__ __forceinline__ void ldsm_x4(uint32_t r[4], const void* p) {
    uint32_t s = (uint32_t)__cvta_generic_to_shared(p);
    asm volatile("ldmatrix.sync.aligned.m8n8.x4.shared.b16 {%0,%1,%2,%3}, [%4];\n"
                 : "=r"(r[0]), "=r"(r[1]), "=r"(r[2]), "=r"(r[3]) : "r"(s));
}
__device__ __forceinline__ void cp16(void* dst, const void* src, bool pred) {
    uint32_t d = (uint32_t)__cvta_generic_to_shared(dst);
    int sz = pred ? 16 : 0;
    asm volatile("cp.async.cg.shared.global [%0], [%1], 16, %2;\n"
                 :: "r"(d), "l"(src), "r"(sz));
}

template <int MODE>
__global__ __launch_bounds__(256, 2) void hgemm(
    const __half* __restrict__ A, int lda,
    const __half* __restrict__ W,
    const float* __restrict__ bias,
    const float* __restrict__ resid,
    float* __restrict__ Cf, __half* __restrict__ Ch,
    int M, int N, int K)
{
    __shared__ __half As[2][128][ROWH];
    __shared__ __half Ws[2][128][ROWH];

    int tid  = threadIdx.x;
    int warp = tid >> 5, lane = tid & 31;
    int g = lane >> 2, t = lane & 3;
    int wm = warp >> 1, wn = warp & 1;
    int row0 = blockIdx.y * 128;
    int col0 = blockIdx.x * 128;

    int lrow = tid >> 1;
    int lch  = (tid & 1) * 16;
    const __half* Ag = A + (size_t)(row0 + lrow) * lda + lch;
    int wnrow = col0 + lrow;
    bool wok = (wnrow < N);
    const __half* Wg = W + (size_t)(wok ? wnrow : 0) * K + lch;

    int brow_off = ((lane >> 4) << 3) + (lane & 7);
    int bcol_off = ((lane >> 3) & 1) * 8;

    float acc[2][8][4];
#pragma unroll
    for (int i = 0; i < 2; i++)
#pragma unroll
        for (int j = 0; j < 8; j++)
#pragma unroll
            for (int q = 0; q < 4; q++) acc[i][j][q] = 0.f;

#define LOADST(k0, b)                                                     \
    {                                                                     \
        cp16(&As[b][lrow][lch + 0], Ag + (k0) + 0, true);                 \
        cp16(&As[b][lrow][lch + 8], Ag + (k0) + 8, true);                 \
        cp16(&Ws[b][lrow][lch + 0], Wg + (k0) + 0, wok);                  \
        cp16(&Ws[b][lrow][lch + 8], Wg + (k0) + 8, wok);                  \
        asm volatile("cp.async.commit_group;\n");                         \
    }

#define COMPUTE(b)                                                        \
    {                                                                     \
        _Pragma("unroll")                                                 \
        for (int ks = 0; ks < BKH; ks += 16) {                            \
            uint32_t af[2][4], bf[8][2];                                  \
            _Pragma("unroll")                                             \
            for (int i = 0; i < 2; i++)                                   \
                ldsm_x4(af[i], &As[b][wm * 32 + i * 16 + (lane & 15)]     \
                                   [ks + (lane >> 4) * 8]);               \
            _Pragma("unroll")                                             \
            for (int p = 0; p < 4; p++) {                                 \
                uint32_t br[4];                                           \
                ldsm_x4(br, &Ws[b][wn * 64 + p * 16 + brow_off]           \
                                  [ks + bcol_off]);                       \
                bf[2 * p + 0][0] = br[0];                                 \
                bf[2 * p + 0][1] = br[1];                                 \
                bf[2 * p + 1][0] = br[2];                                 \
                bf[2 * p + 1][1] = br[3];                                 \
            }                                                             \
            _Pragma("unroll")                                             \
            for (int i = 0; i < 2; i++)                                   \
                _Pragma("unroll")                                         \
                for (int j = 0; j < 8; j++)                               \
                    mma_f16(acc[i][j], af[i], bf[j]);                     \
        }                                                                 \
    }

    LOADST(0, 0);
    int buf = 0;
    for (int k0 = BKH; k0 < K; k0 += BKH) {
        LOADST(k0, buf ^ 1);
        asm volatile("cp.async.wait_group 1;\n");
        __syncthreads();
        COMPUTE(buf);
        __syncthreads();
        buf ^= 1;
    }
    asm volatile("cp.async.wait_group 0;\n");
    __syncthreads();
    COMPUTE(buf);

#pragma unroll
    for (int i = 0; i < 2; i++) {
#pragma unroll
        for (int j = 0; j < 8; j++) {
            int col = col0 + wn * 64 + j * 8 + 2 * t;
            if (col >= N) continue;
            float b0v = 0.f, b1v = 0.f;
            if (MODE == 1 || MODE == 2 || MODE == 3) { b0v = bias[col]; b1v = bias[col + 1]; }
#pragma unroll
            for (int h = 0; h < 2; h++) {
                int row = row0 + wm * 32 + i * 16 + g + h * 8;
                size_t oidx = (size_t)row * N + col;
                float v0 = acc[i][j][2 * h + 0];
                float v1 = acc[i][j][2 * h + 1];
                if (MODE == 1) {
                    v0 = gelu_tanh_f(v0 + b0v); v1 = gelu_tanh_f(v1 + b1v);
                    *(__half2*)(Ch + oidx) = __floats2half2_rn(v0, v1);
                } else if (MODE == 2) {
                    float2 rr = *(const float2*)(resid + oidx);
                    *(float2*)(Cf + oidx) = make_float2(rr.x + v0 + b0v, rr.y + v1 + b1v);
                } else if (MODE == 3) {
                    *(float2*)(Cf + oidx) = make_float2(softplus_f(v0 + b0v),
                                                        softplus_f(v1 + b1v));
                } else if (MODE == 4) {
                    *(float2*)(Cf + oidx) = make_float2(v0, v1);
                    *(__half2*)(Ch + oidx) = __floats2half2_rn(v0, v1);
                } else {
                    *(float2*)(Cf + oidx) = make_float2(v0, v1);
                }
            }
        }
    }
#undef LOADST
#undef COMPUTE
}

// ---------------- depthwise causal conv (D_CONV=4) + silu -------------------
__global__ __launch_bounds__(256) void conv_silu_kernel(
    const float* __restrict__ XZ, const float* __restrict__ conv_w,
    const float* __restrict__ conv_b, float* __restrict__ XC,
    __half* __restrict__ XCh)
{
    size_t idx = (size_t)blockIdx.x * blockDim.x + threadIdx.x;
    if (idx >= (size_t)MM * DI) return;
    int d = (int)(idx & (DI - 1));
    int m = (int)(idx >> 10);
    int t = m & (LL - 1);
    int mb = m - t;
    float acc = conv_b[d];
#pragma unroll
    for (int k = 0; k < 4; k++) {
        int tt = t - 3 + k;
        if (tt >= 0)
            acc = fmaf(conv_w[d * 4 + k], XZ[(size_t)(mb + tt) * (2 * DI) + d], acc);
    }
    float r = silu_f(acc);
    XC[idx] = r;
    XCh[idx] = __float2half(r);
}

// ---------------- segmented selective scan: THREAD-PER-CHANNEL ---------------
// warp wg -> (b, grp, seg): seg = wg & (SEGS-1), grp = (wg/SEGS) & 31, b = top
// lane owns channel d = grp*32 + lane; 16 states in registers.

// Pass 1: from h=0 over segment -> SegH (partial state), SegP (prod dA)
__global__ __launch_bounds__(256) void scan_part1(
    const float* __restrict__ DT, const float* __restrict__ XC,
    const float* __restrict__ PROJ, const float* __restrict__ A_log)
{
    int wg = (blockIdx.x * blockDim.x + threadIdx.x) >> 5;  // 0..2047
    int lane = threadIdx.x & 31;
    int seg = wg & (SEGS - 1);
    int grp = (wg / SEGS) & 31;
    int b = wg / (SEGS * 32);
    int d = grp * 32 + lane;

    float An[NS];
#pragma unroll
    for (int n = 0; n < NS; n++) An[n] = -expf(A_log[d * NS + n]);

    size_t rowbase = (size_t)b * LL + (size_t)seg * SEGL;
    const float* dtp = DT + rowbase * DI + d;
    const float* xcp = XC + rowbase * DI + d;
    const float* bcp = PROJ + rowbase * PROJC + RR + lane;

    float h[NS], P[NS];
#pragma unroll
    for (int n = 0; n < NS; n++) { h[n] = 0.f; P[n] = 1.f; }

    float cdt[TBS], cxc[TBS], cbc[TBS];
    float ndt[TBS] = {0}, nxc[TBS] = {0}, nbc[TBS] = {0};
#pragma unroll
    for (int i = 0; i < TBS; i++) {
        cdt[i] = __ldg(dtp + i * DI);
        cxc[i] = __ldg(xcp + i * DI);
        cbc[i] = __ldg(bcp + i * PROJC);
    }
    const int NB = SEGL / TBS;
    for (int blk = 0; blk < NB; blk++) {
        if (blk + 1 < NB) {
            const float* dtn = dtp + (blk + 1) * TBS * DI;
            const float* xcn = xcp + (blk + 1) * TBS * DI;
            const float* bcn = bcp + (blk + 1) * TBS * PROJC;
#pragma unroll
            for (int i = 0; i < TBS; i++) {
                ndt[i] = __ldg(dtn + i * DI);
                nxc[i] = __ldg(xcn + i * DI);
                nbc[i] = __ldg(bcn + i * PROJC);
            }
        }
#pragma unroll
        for (int i = 0; i < TBS; i++) {
            float dt = cdt[i];
            float u = dt * cxc[i];
            float bcv = cbc[i];
#pragma unroll
            for (int n = 0; n < NS; n++) {
                float Bn = __shfl_sync(0xffffffffu, bcv, n);
                float dA = __expf(dt * An[n]);
                P[n] *= dA;
                h[n] = fmaf(dA, h[n], u * Bn);
            }
        }
#pragma unroll
        for (int i = 0; i < TBS; i++) { cdt[i] = ndt[i]; cxc[i] = nxc[i]; cbc[i] = nbc[i]; }
    }
    size_t idx = ((((size_t)b * SEGS + seg) * DI) + d) * NS;
#pragma unroll
    for (int n = 0; n < NS; n += 4) {
        *(float4*)(g_SegH + idx + n) = make_float4(h[n], h[n+1], h[n+2], h[n+3]);
        *(float4*)(g_SegP + idx + n) = make_float4(P[n], P[n+1], P[n+2], P[n+3]);
    }
}

// Pass 2: sequential combine across segments
__global__ __launch_bounds__(256) void scan_part2()
{
    int tid = blockIdx.x * blockDim.x + threadIdx.x;   // 0..32767
    int n = tid & (NS - 1);
    int d = (tid >> 4) & (DI - 1);
    int b = tid >> 14;
    float h = 0.f;
#pragma unroll
    for (int s = 0; s < SEGS; s++) {
        size_t idx = ((((size_t)b * SEGS + s) * DI) + d) * NS + n;
        g_SegI[idx] = h;
        h = fmaf(g_SegP[idx], h, g_SegH[idx]);
    }
}

// Pass 3: re-run segment with h_init, produce y
__global__ __launch_bounds__(256) void scan_part3(
    const float* __restrict__ DT, const float* __restrict__ XC,
    const float* __restrict__ PROJ, const float* __restrict__ XZ,
    const float* __restrict__ A_log, const float* __restrict__ D_param,
    __half* __restrict__ Y)
{
    int wg = (blockIdx.x * blockDim.x + threadIdx.x) >> 5;  // 0..2047
    int lane = threadIdx.x & 31;
    int seg = wg & (SEGS - 1);
    int grp = (wg / SEGS) & 31;
    int b = wg / (SEGS * 32);
    int d = grp * 32 + lane;

    float An[NS];
#pragma unroll
    for (int n = 0; n < NS; n++) An[n] = -expf(A_log[d * NS + n]);
    float Dp = D_param[d];

    size_t rowbase = (size_t)b * LL + (size_t)seg * SEGL;
    const float* dtp = DT + rowbase * DI + d;
    const float* xcp = XC + rowbase * DI + d;
    const float* zp  = XZ + rowbase * (2 * DI) + DI + d;
    const float* bcp = PROJ + rowbase * PROJC + RR + lane;
    __half* yp = Y + rowbase * DI + d;

    float h[NS];
    {
        size_t idx = ((((size_t)b * SEGS + seg) * DI) + d) * NS;
#pragma unroll
        for (int n = 0; n < NS; n += 4) {
            float4 v = *(const float4*)(g_SegI + idx + n);
            h[n] = v.x; h[n+1] = v.y; h[n+2] = v.z; h[n+3] = v.w;
        }
    }

    float cdt[TBS], cxc[TBS], czv[TBS], cbc[TBS];
    float ndt[TBS] = {0}, nxc[TBS] = {0}, nzv[TBS] = {0}, nbc[TBS] = {0};
#pragma unroll
    for (int i = 0; i < TBS; i++) {
        cdt[i] = __ldg(dtp + i * DI);
        cxc[i] = __ldg(xcp + i * DI);
        czv[i] = __ldg(zp + i * 2 * DI);
        cbc[i] = __ldg(bcp + i * PROJC);
    }
    const int NB = SEGL / TBS;
    for (int blk = 0; blk < NB; blk++) {
        if (blk + 1 < NB) {
            const float* dtn = dtp + (blk + 1) * TBS * DI;
            const float* xcn = xcp + (blk + 1) * TBS * DI;
            const float* zn  = zp  + (blk + 1) * TBS * 2 * DI;
            const float* bcn = bcp + (blk + 1) * TBS * PROJC;
#pragma unroll
            for (int i = 0; i < TBS; i++) {
                ndt[i] = __ldg(dtn + i * DI);
                nxc[i] = __ldg(xcn + i * DI);
                nzv[i] = __ldg(zn + i * 2 * DI);
                nbc[i] = __ldg(bcn + i * PROJC);
            }
        }
        __half* yb = yp + blk * TBS * DI;
#pragma unroll
        for (int i = 0; i < TBS; i++) {
            float dt = cdt[i], xc = cxc[i];
            float u = dt * xc;
            float bcv = cbc[i];
            float y = 0.f;
#pragma unroll
            for (int n = 0; n < NS; n++) {
                float Bn = __shfl_sync(0xffffffffu, bcv, n);
                float Cn = __shfl_sync(0xffffffffu, bcv, NS + n);
                float dA = __expf(dt * An[n]);
                h[n] = fmaf(dA, h[n], u * Bn);
                y = fmaf(h[n], Cn, y);
            }
            y = fmaf(Dp, xc, y);
            yb[i * DI] = __float2half(y * silu_f(czv[i]));
        }
#pragma unroll
        for (int i = 0; i < TBS; i++) {
            cdt[i] = ndt[i]; cxc[i] = nxc[i]; czv[i] = nzv[i]; cbc[i] = nbc[i];
        }
    }
}

// ---------------- residual add with gather ----------------------------------
__global__ __launch_bounds__(256) void add_gather_kernel(
    const float* __restrict__ X, const float* __restrict__ OUTP,
    const int* __restrict__ path_rev, float* __restrict__ XNEW)
{
    size_t idx = (size_t)blockIdx.x * blockDim.x + threadIdx.x;
    if (idx >= (size_t)MM * DD) return;
    int d = (int)(idx & (DD - 1));
    int m = (int)(idx >> 10);
    int b = m >> 12, t = m & (LL - 1);
    int src = (b << 12) + path_rev[t];
    XNEW[idx] = X[idx] + OUTP[(size_t)src * DD + d];
}

// ---------------- launch -----------------------------------------------------
extern "C" void kernel_launch(void* const* d_in, const int* in_sizes, int n_in,
                              void* d_out, int out_size)
{
    const float* x          = (const float*)d_in[0];
    const int*   path       = (const int*)  d_in[1];
    const int*   path_rev   = (const int*)  d_in[2];
    const float* in_proj_w  = (const float*)d_in[3];
    const float* conv_w     = (const float*)d_in[4];
    const float* conv_b     = (const float*)d_in[5];
    const float* x_proj_w   = (const float*)d_in[6];
    const float* dt_proj_w  = (const float*)d_in[7];
    const float* dt_proj_b  = (const float*)d_in[8];
    const float* A_log      = (const float*)d_in[9];
    const float* D_param    = (const float*)d_in[10];
    const float* out_proj_w = (const float*)d_in[11];
    const float* fc1_w      = (const float*)d_in[12];
    const float* fc1_b      = (const float*)d_in[13];
    const float* fc2_w      = (const float*)d_in[14];
    const float* fc2_b      = (const float*)d_in[15];
    float* out = (float*)d_out;

    __half *Uh, *XCh, *PROJh, *Yh, *HNh, *Gh;
    __half *Wip, *Wxp, *Wdt, *Wop, *Wf1, *Wf2;
    float *XZ, *XC, *PROJ, *DT, *OUTP, *XNEW;
    cudaGetSymbolAddress((void**)&Uh,    g_Uh);
    cudaGetSymbolAddress((void**)&XZ,    g_XZ);
    cudaGetSymbolAddress((void**)&XC,    g_XC);
    cudaGetSymbolAddress((void**)&XCh,   g_XCh);
    cudaGetSymbolAddress((void**)&PROJ,  g_PROJ);
    cudaGetSymbolAddress((void**)&PROJh, g_PROJh);
    cudaGetSymbolAddress((void**)&DT,    g_DT);
    cudaGetSymbolAddress((void**)&Yh,    g_Yh);
    cudaGetSymbolAddress((void**)&OUTP,  g_OUTP);
    cudaGetSymbolAddress((void**)&XNEW,  g_XNEW);
    cudaGetSymbolAddress((void**)&HNh,   g_HNh);
    cudaGetSymbolAddress((void**)&Gh,    g_Gh);
    cudaGetSymbolAddress((void**)&Wip,   g_Wip);
    cudaGetSymbolAddress((void**)&Wxp,   g_Wxp);
    cudaGetSymbolAddress((void**)&Wdt,   g_Wdt);
    cudaGetSymbolAddress((void**)&Wop,   g_Wop);
    cudaGetSymbolAddress((void**)&Wf1,   g_Wf1);
    cudaGetSymbolAddress((void**)&Wf2,   g_Wf2);

    auto cvt = [&](const float* s, __half* d, int n) {
        f2h_kernel<<<(n / 4 + 255) / 256, 256>>>(s, d, n);
    };

    // 0: f2h Wip
    cvt(in_proj_w,  Wip, 2 * DI * DD);
    // 1: u = LN(x[:, path, :]) -> fp16
    ln_kernel<<<MM, 256>>>(x, path, Uh);
    // 2: f2h Wxp
    cvt(x_proj_w,   Wxp, PROJC * DI);
    // 3: xz = u @ in_proj_w^T   (8192 x 2048, K=1024) -> f32   *** profiled ***
    hgemm<0><<<dim3(2 * DI / 128, MM / 128), 256>>>(
        Uh, DD, Wip, nullptr, nullptr, XZ, nullptr, MM, 2 * DI, DD);
    // 4: conv + silu -> f32 + f16
    conv_silu_kernel<<<(int)(((size_t)MM * DI + 255) / 256), 256>>>(XZ, conv_w, conv_b, XC, XCh);
    // 5: f2h Wdt
    cvt(dt_proj_w,  Wdt, DI * RR);
    // 6: proj = xc @ x_proj_w^T   (8192 x 96, K=1024) -> f32 + f16
    hgemm<4><<<dim3(1, MM / 128), 256>>>(
        XCh, DI, Wxp, nullptr, nullptr, PROJ, PROJh, MM, PROJC, DI);
    // 7: dt = softplus(proj[:, :64] @ dt_proj_w^T + b)   (8192 x 1024, K=64)
    hgemm<3><<<dim3(DI / 128, MM / 128), 256>>>(
        PROJh, PROJC, Wdt, dt_proj_b, nullptr, DT, nullptr, MM, DI, RR);
    // 8-10: segmented thread-per-channel scan -> Yh
    scan_part1<<<(BB * SEGS * 32 * 32) / 256, 256>>>(DT, XC, PROJ, A_log);
    scan_part2<<<(BB * DI * NS) / 256, 256>>>();
    scan_part3<<<(BB * SEGS * 32 * 32) / 256, 256>>>(DT, XC, PROJ, XZ, A_log, D_param, Yh);
    // 11: f2h Wop
    cvt(out_proj_w, Wop, DD * DI);
    // 12: OUTP = Y @ out_proj_w^T   (8192 x 1024, K=1024) -> f32
    hgemm<0><<<dim3(DD / 128, MM / 128), 256>>>(
        Yh, DI, Wop, nullptr, nullptr, OUTP, nullptr, MM, DD, DI);
    // 13: xnew = x + OUTP[:, path_rev, :]
    add_gather_kernel<<<(int)(((size_t)MM * DD + 255) / 256), 256>>>(x, OUTP, path_rev, XNEW);
    // 14: hn = LN(xnew) -> fp16
    ln_kernel<<<MM, 256>>>(XNEW, nullptr, HNh);
    // 15: f2h Wf1
    cvt(fc1_w,      Wf1, HH * DD);
    // 16: G = gelu(hn @ fc1_w^T + fc1_b)   (8192 x 4096, K=1024) -> fp16
    hgemm<1><<<dim3(HH / 128, MM / 128), 256>>>(
        HNh, DD, Wf1, fc1_b, nullptr, nullptr, Gh, MM, HH, DD);
    // 17: f2h Wf2
    cvt(fc2_w,      Wf2, DD * HH);
    // 18: out = xnew + G @ fc2_w^T + fc2_b   (8192 x 1024, K=4096)
    hgemm<2><<<dim3(DD / 128, MM / 128), 256>>>(
        Gh, HH, Wf2, fc2_b, XNEW, out, nullptr, MM, DD, HH);
}